// round 6
// baseline (speedup 1.0000x reference)
#include <cuda_runtime.h>

#define NB 4
#define NQS 512
#define NKS 1024
#define DD 64

typedef unsigned long long ull;

#define ADD2(o,a,b)   asm("add.rn.f32x2 %0, %1, %2;" : "=l"(o) : "l"(a), "l"(b))
#define FMA2(o,a,b,c) asm("fma.rn.f32x2 %0, %1, %2, %3;" : "=l"(o) : "l"(a), "l"(b), "l"(c))
#define ABSM 0x7FFFFFFF7FFFFFFFULL

// smem layout (floats) for attn kernel
#define S_STRIDE 1032
#define S_OFF    0                       // 4*1032 = 4128 (logits; later aliased as RED)
#define PD_STRIDE 2056
#define PD_OFF   4128                    // 4*2056 = 8224 (duplicated P pairs)
#define QD_OFF   (PD_OFF + 8224)        // 12352: 64*8 negated+duplicated q
#define MP_OFF   (QD_OFF + 512)         // 12864: 8 max partials
#define SP_OFF   (MP_OFF + 8)           // 12872: 8 sum partials
#define SMEM_FLOATS (SP_OFF + 8)        // 12880 -> 51520 B

// Scratch: k transposed per batch (kT[b][d][j]); q row-major.
__device__ __align__(16) float g_kT[NB * DD * NKS];
__device__ __align__(16) float g_q [NB * NQS * DD];

// ---------------------------------------------------------------------------
// MLP kernel (R5 version — kept): 32 rows/block, 256 thr = 32 rows x 8 slices.
// Grid 192: [0,128) key path, [128,192) query path.
// Key-path output staged in smem and written TRANSPOSED but COALESCED.
// ---------------------------------------------------------------------------
__device__ __forceinline__ void mlp_layer(const float* __restrict__ in_row,
                                          const float* __restrict__ Ws, int sl,
                                          const float* __restrict__ bs,
                                          float4 acc[2])
{
    acc[0] = ((const float4*)bs)[sl * 2 + 0];
    acc[1] = ((const float4*)bs)[sl * 2 + 1];
#pragma unroll 8
    for (int din = 0; din < 64; din++) {
        float xv = in_row[din];
        const float4* wr = (const float4*)(Ws + din * 64) + sl * 2;
        float4 w0 = wr[0], w1 = wr[1];
        acc[0].x = fmaf(xv, w0.x, acc[0].x);
        acc[0].y = fmaf(xv, w0.y, acc[0].y);
        acc[0].z = fmaf(xv, w0.z, acc[0].z);
        acc[0].w = fmaf(xv, w0.w, acc[0].w);
        acc[1].x = fmaf(xv, w1.x, acc[1].x);
        acc[1].y = fmaf(xv, w1.y, acc[1].y);
        acc[1].z = fmaf(xv, w1.z, acc[1].z);
        acc[1].w = fmaf(xv, w1.w, acc[1].w);
    }
}

__global__ __launch_bounds__(256) void mlp_kernel(
    const float* __restrict__ x1, const float* __restrict__ x2,
    const float* __restrict__ Wk1, const float* __restrict__ bk1,
    const float* __restrict__ Wk2, const float* __restrict__ bk2,
    const float* __restrict__ Wq1, const float* __restrict__ bq1,
    const float* __restrict__ Wq2, const float* __restrict__ bq2)
{
    extern __shared__ float sm[];
    float* W1s = sm;             // 4096
    float* W2s = sm + 4096;      // 4096
    float* b1s = sm + 8192;      // 64
    float* b2s = sm + 8256;      // 64
    float* xs  = sm + 8320;      // 32*65 = 2080
    float* hs  = sm + 10400;     // 2080
    // total 12480 floats = 49920 B

    const int t = threadIdx.x;
    const bool keypath = blockIdx.x < 128;
    const float *x, *W1, *b1, *W2, *b2;
    int row0;
    if (keypath) { x = x1; W1 = Wk1; b1 = bk1; W2 = Wk2; b2 = bk2; row0 = blockIdx.x * 32; }
    else         { x = x2; W1 = Wq1; b1 = bq1; W2 = Wq2; b2 = bq2; row0 = (blockIdx.x - 128) * 32; }

    for (int idx = t; idx < 1024; idx += 256) {
        ((float4*)W1s)[idx] = ((const float4*)W1)[idx];
        ((float4*)W2s)[idx] = ((const float4*)W2)[idx];
    }
    if (t < 16) {
        ((float4*)b1s)[t] = ((const float4*)b1)[t];
        ((float4*)b2s)[t] = ((const float4*)b2)[t];
    }
#pragma unroll
    for (int u = t; u < 512; u += 256) {
        int rr = u >> 4, c = u & 15;
        float4 v = ((const float4*)(x + (size_t)(row0 + rr) * DD))[c];
        xs[rr * 65 + c * 4 + 0] = v.x;
        xs[rr * 65 + c * 4 + 1] = v.y;
        xs[rr * 65 + c * 4 + 2] = v.z;
        xs[rr * 65 + c * 4 + 3] = v.w;
    }
    __syncthreads();

    const int row = t >> 3, sl = t & 7;

    float4 acc[2];
    mlp_layer(xs + row * 65, W1s, sl, b1s, acc);   // layer 1
    {
        float* h = hs + row * 65 + sl * 8;
        h[0] = fmaxf(acc[0].x, 0.f); h[1] = fmaxf(acc[0].y, 0.f);
        h[2] = fmaxf(acc[0].z, 0.f); h[3] = fmaxf(acc[0].w, 0.f);
        h[4] = fmaxf(acc[1].x, 0.f); h[5] = fmaxf(acc[1].y, 0.f);
        h[6] = fmaxf(acc[1].z, 0.f); h[7] = fmaxf(acc[1].w, 0.f);
    }
    __syncthreads();
    mlp_layer(hs + row * 65, W2s, sl, b2s, acc);   // layer 2 (no relu)

    if (keypath) {
        __syncthreads();
        {
            float* o = xs + row * 65 + sl * 8;
            o[0] = acc[0].x; o[1] = acc[0].y; o[2] = acc[0].z; o[3] = acc[0].w;
            o[4] = acc[1].x; o[5] = acc[1].y; o[6] = acc[1].z; o[7] = acc[1].w;
        }
        __syncthreads();
        const int b  = row0 >> 10;
        const int j0 = row0 & 1023;
        float* o = g_kT + (size_t)b * DD * NKS + j0;
#pragma unroll
        for (int u = 0; u < 8; u++) {
            int idx = u * 256 + t;
            int d = idx >> 5, j = idx & 31;
            o[(size_t)d * NKS + j] = xs[j * 65 + d];
        }
    } else {
        const int rg = row0 + row;
        float4* o = (float4*)(g_q + (size_t)rg * DD) + sl * 2;
        o[0] = acc[0]; o[1] = acc[1];
    }
}

// ---------------------------------------------------------------------------
// Attention (R4 version — reverted): one block = (b, 4 queries), 256 thr,
// grid (128,4) = 512 CTAs, occupancy 4.
// ---------------------------------------------------------------------------
__global__ __launch_bounds__(256, 4) void attn_kernel(
    const float* __restrict__ rv, float* __restrict__ out)
{
    extern __shared__ float sm[];
    float* S    = sm + S_OFF;      // [4][1032] logits (aliased later as RED)
    float* PD   = sm + PD_OFF;     // [4][2056] duplicated P pairs
    float* QD   = sm + QD_OFF;     // [64][8] (-q) duplicated pairs
    float* Mp   = sm + MP_OFF;     // [4][2] max partials
    float* Sp   = sm + SP_OFF;     // [4][2] sum partials

    const int b    = blockIdx.y;
    const int qt   = blockIdx.x;
    const int t    = threadIdx.x;
    const int lane = t & 31;
    const int w    = t >> 5;

    // stage QD[d][2i..2i+1] = -q[i][d] (negated + duplicated)
    {
        const int d = t >> 2, i = t & 3;
        float v = g_q[(size_t)(b * NQS + qt * 4 + i) * DD + d];
        QD[d * 8 + 2 * i + 0] = -v;
        QD[d * 8 + 2 * i + 1] = -v;
    }
    __syncthreads();

    const float* kTg = g_kT + (size_t)b * DD * NKS;

    // -------- Phase 1: logits, 2 independent key-pair chains per thread ----
    {
        const int j0 = w * 64 + 2 * lane;
        const int j1 = 512 + j0;
        const float* kp0 = kTg + j0;
        const float* kp1 = kTg + j1;

        ull a00 = 0, a01 = 0, a02 = 0, a03 = 0;
        ull a10 = 0, a11 = 0, a12 = 0, a13 = 0;
#pragma unroll 4
        for (int d = 0; d < 64; d++) {
            ull kA = *(const ull*)(kp0 + (size_t)d * NKS);
            ull kB = *(const ull*)(kp1 + (size_t)d * NKS);
            ulonglong2 nq01 = *(const ulonglong2*)(QD + d * 8);
            ulonglong2 nq23 = *(const ulonglong2*)(QD + d * 8 + 4);
            ull u;
            ADD2(u, kA, nq01.x); u &= ABSM; ADD2(a00, a00, u);
            ADD2(u, kA, nq01.y); u &= ABSM; ADD2(a01, a01, u);
            ADD2(u, kA, nq23.x); u &= ABSM; ADD2(a02, a02, u);
            ADD2(u, kA, nq23.y); u &= ABSM; ADD2(a03, a03, u);
            ADD2(u, kB, nq01.x); u &= ABSM; ADD2(a10, a10, u);
            ADD2(u, kB, nq01.y); u &= ABSM; ADD2(a11, a11, u);
            ADD2(u, kB, nq23.x); u &= ABSM; ADD2(a12, a12, u);
            ADD2(u, kB, nq23.y); u &= ABSM; ADD2(a13, a13, u);
        }
        const ull accA[4] = {a00, a01, a02, a03};
        const ull accB[4] = {a10, a11, a12, a13};
#pragma unroll
        for (int q = 0; q < 4; q++) {
            ull a = accA[q], bq = accB[q];
            *(float2*)(S + q * S_STRIDE + j0) =
                make_float2(-__uint_as_float((unsigned)a),
                            -__uint_as_float((unsigned)(a >> 32)));
            *(float2*)(S + q * S_STRIDE + j1) =
                make_float2(-__uint_as_float((unsigned)bq),
                            -__uint_as_float((unsigned)(bq >> 32)));
        }
    }
    __syncthreads();

    // -------- Phase 2: softmax, 2 warps per row --------
    {
        const int row  = w >> 1;
        const int half = w & 1;
        const float* Srow = S + row * S_STRIDE + half * 512;
        float* Prow = PD + row * PD_STRIDE + half * 1024;

        float m = -3.0e38f;
#pragma unroll
        for (int it = 0; it < 16; it++) m = fmaxf(m, Srow[it * 32 + lane]);
#pragma unroll
        for (int o = 16; o; o >>= 1) m = fmaxf(m, __shfl_xor_sync(0xffffffffu, m, o));
        if (lane == 0) Mp[row * 2 + half] = m;
        __syncthreads();
        const float M = fmaxf(Mp[row * 2], Mp[row * 2 + 1]);

        float sum = 0.f;
#pragma unroll
        for (int it = 0; it < 16; it++) {
            float p = __expf(Srow[it * 32 + lane] - M);
            *(float2*)(Prow + 2 * (it * 32 + lane)) = make_float2(p, p);
            sum += p;
        }
#pragma unroll
        for (int o = 16; o; o >>= 1) sum += __shfl_xor_sync(0xffffffffu, sum, o);
        if (lane == 0) Sp[row * 2 + half] = sum;
    }
    __syncthreads();

    // -------- Phase 3: O = P @ r via FFMA2, 8-way K split --------
    const int kg = t >> 5;
    const int qg = (t >> 4) & 1;
    const int dg = t & 15;
    const float* rb  = rv + (size_t)b * NKS * DD + (size_t)kg * 128 * DD + dg * 4;
    const float* PD0 = PD + (qg * 2 + 0) * PD_STRIDE + kg * 256;
    const float* PD1 = PD + (qg * 2 + 1) * PD_STRIDE + kg * 256;

    ull aA0 = 0, aA1 = 0, aB0 = 0, aB1 = 0;
#pragma unroll 4
    for (int kk = 0; kk < 128; kk++) {
        ull p0 = *(const ull*)(PD0 + 2 * kk);
        ull p1 = *(const ull*)(PD1 + 2 * kk);
        ulonglong2 r2 = *(const ulonglong2*)(rb + (size_t)kk * DD);
        FMA2(aA0, p0, r2.x, aA0);
        FMA2(aA1, p0, r2.y, aA1);
        FMA2(aB0, p1, r2.x, aB0);
        FMA2(aB1, p1, r2.y, aB1);
    }

    float4* RED = (float4*)sm;
    {
        float4 vA = make_float4(__uint_as_float((unsigned)aA0),
                                __uint_as_float((unsigned)(aA0 >> 32)),
                                __uint_as_float((unsigned)aA1),
                                __uint_as_float((unsigned)(aA1 >> 32)));
        float4 vB = make_float4(__uint_as_float((unsigned)aB0),
                                __uint_as_float((unsigned)(aB0 >> 32)),
                                __uint_as_float((unsigned)aB1),
                                __uint_as_float((unsigned)(aB1 >> 32)));
        RED[kg * 64 + (qg * 2 + 0) * 16 + dg] = vA;
        RED[kg * 64 + (qg * 2 + 1) * 16 + dg] = vB;
    }
    __syncthreads();

    if (t < 64) {
        const int q = t >> 4, dd = t & 15;
        float4 s = RED[q * 16 + dd];
#pragma unroll
        for (int g = 1; g < 8; g++) {
            float4 v = RED[g * 64 + q * 16 + dd];
            s.x += v.x; s.y += v.y; s.z += v.z; s.w += v.w;
        }
        const float li = 1.0f / (Sp[q * 2] + Sp[q * 2 + 1]);
        s.x *= li; s.y *= li; s.z *= li; s.w *= li;
        ((float4*)(out + (size_t)(b * NQS + qt * 4 + q) * DD))[dd] = s;
    }
}

// ---------------------------------------------------------------------------
extern "C" void kernel_launch(void* const* d_in, const int* in_sizes, int n_in,
                              void* d_out, int out_size)
{
    const float* x1  = (const float*)d_in[0];
    const float* x2  = (const float*)d_in[1];
    const float* r   = (const float*)d_in[2];
    const float* Wk1 = (const float*)d_in[3];
    const float* bk1 = (const float*)d_in[4];
    const float* Wk2 = (const float*)d_in[5];
    const float* bk2 = (const float*)d_in[6];
    const float* Wq1 = (const float*)d_in[7];
    const float* bq1 = (const float*)d_in[8];
    const float* Wq2 = (const float*)d_in[9];
    const float* bq2 = (const float*)d_in[10];
    float* out = (float*)d_out;

    cudaFuncSetAttribute(mlp_kernel,  cudaFuncAttributeMaxDynamicSharedMemorySize, 49920);
    cudaFuncSetAttribute(attn_kernel, cudaFuncAttributeMaxDynamicSharedMemorySize, SMEM_FLOATS * 4);

    mlp_kernel<<<192, 256, 49920>>>(x1, x2, Wk1, bk1, Wk2, bk2, Wq1, bq1, Wq2, bq2);
    attn_kernel<<<dim3(128, 4), 256, SMEM_FLOATS * 4>>>(r, out);
}

// round 7
// speedup vs baseline: 1.2697x; 1.2697x over previous
#include <cuda_runtime.h>

#define NB 4
#define NQS 512
#define NKS 1024
#define DD 64
#define NCTAS 512

typedef unsigned long long ull;

#define ADD2(o,a,b)   asm("add.rn.f32x2 %0, %1, %2;" : "=l"(o) : "l"(a), "l"(b))
#define FMA2(o,a,b,c) asm("fma.rn.f32x2 %0, %1, %2, %3;" : "=l"(o) : "l"(a), "l"(b), "l"(c))
#define ABSM 0x7FFFFFFF7FFFFFFFULL

// smem layout (floats): attn phase (MLP phase reuses the same buffer, <11K floats)
#define S_STRIDE 1032
#define S_OFF    0
#define PD_STRIDE 2056
#define PD_OFF   4128
#define QD_OFF   (PD_OFF + 8224)        // 12352
#define MP_OFF   (QD_OFF + 512)         // 12864
#define SP_OFF   (MP_OFF + 8)           // 12872
#define SMEM_FLOATS (SP_OFF + 8)        // 12880 -> 51520 B

// Scratch: k transposed per batch (kT[b][d][j]); q row-major.
__device__ __align__(16) float g_kT[NB * DD * NKS];
__device__ __align__(16) float g_q [NB * NQS * DD];

// grid barrier state (replay-safe: g_cnt self-resets, g_sense is monotonic)
__device__ unsigned g_cnt   = 0;
__device__ unsigned g_sense = 0;

__global__ __launch_bounds__(256, 4) void fused_kernel(
    const float* __restrict__ x1, const float* __restrict__ x2,
    const float* __restrict__ rv,
    const float* __restrict__ Wk1, const float* __restrict__ bk1,
    const float* __restrict__ Wk2, const float* __restrict__ bk2,
    const float* __restrict__ Wq1, const float* __restrict__ bq1,
    const float* __restrict__ Wq2, const float* __restrict__ bq2,
    float* __restrict__ out)
{
    extern __shared__ float sm[];
    const int bid  = blockIdx.x;
    const int t    = threadIdx.x;
    const int lane = t & 31;
    const int w    = t >> 5;

    // ===================== Phase A: MLPs (384 CTAs x 16 rows) ==============
    if (bid < 384) {
        float* W1s = sm;             // 4096
        float* W2s = sm + 4096;      // 4096
        float* b1s = sm + 8192;      // 64
        float* b2s = sm + 8256;      // 64
        float* xs  = sm + 8320;      // 16*65 = 1040
        float* hs  = sm + 9360;      // 1040

        const bool keypath = bid < 256;
        const float *x, *W1, *b1, *W2, *b2;
        int row0;
        if (keypath) { x = x1; W1 = Wk1; b1 = bk1; W2 = Wk2; b2 = bk2; row0 = bid * 16; }
        else         { x = x2; W1 = Wq1; b1 = bq1; W2 = Wq2; b2 = bq2; row0 = (bid - 256) * 16; }

        for (int idx = t; idx < 1024; idx += 256) {
            ((float4*)W1s)[idx] = ((const float4*)W1)[idx];
            ((float4*)W2s)[idx] = ((const float4*)W2)[idx];
        }
        if (t < 16) {
            ((float4*)b1s)[t] = ((const float4*)b1)[t];
            ((float4*)b2s)[t] = ((const float4*)b2)[t];
        }
        {   // stage x: 16 rows x 16 float4, one per thread
            int rr = t >> 4, c = t & 15;
            float4 v = ((const float4*)(x + (size_t)(row0 + rr) * DD))[c];
            xs[rr * 65 + c * 4 + 0] = v.x;
            xs[rr * 65 + c * 4 + 1] = v.y;
            xs[rr * 65 + c * 4 + 2] = v.z;
            xs[rr * 65 + c * 4 + 3] = v.w;
        }
        __syncthreads();

        const int row = t >> 4, sl = t & 15;
        const float* in1 = xs + row * 65;

        float4 acc = ((const float4*)b1s)[sl];
#pragma unroll 8
        for (int din = 0; din < 64; din++) {
            float xv = in1[din];
            float4 wv = ((const float4*)W1s)[din * 16 + sl];
            acc.x = fmaf(xv, wv.x, acc.x);
            acc.y = fmaf(xv, wv.y, acc.y);
            acc.z = fmaf(xv, wv.z, acc.z);
            acc.w = fmaf(xv, wv.w, acc.w);
        }
        {
            float* h = hs + row * 65 + sl * 4;
            h[0] = fmaxf(acc.x, 0.f); h[1] = fmaxf(acc.y, 0.f);
            h[2] = fmaxf(acc.z, 0.f); h[3] = fmaxf(acc.w, 0.f);
        }
        __syncthreads();

        const float* in2 = hs + row * 65;
        acc = ((const float4*)b2s)[sl];
#pragma unroll 8
        for (int din = 0; din < 64; din++) {
            float xv = in2[din];
            float4 wv = ((const float4*)W2s)[din * 16 + sl];
            acc.x = fmaf(xv, wv.x, acc.x);
            acc.y = fmaf(xv, wv.y, acc.y);
            acc.z = fmaf(xv, wv.z, acc.z);
            acc.w = fmaf(xv, wv.w, acc.w);
        }

        if (keypath) {
            __syncthreads();
            {   // stage output rows in xs
                float* o = xs + row * 65 + sl * 4;
                o[0] = acc.x; o[1] = acc.y; o[2] = acc.z; o[3] = acc.w;
            }
            __syncthreads();
            // transposed coalesced-ish store: g_kT[b][d][j0+j]
            const int bb = row0 >> 10;
            const int j0 = row0 & 1023;
            float* o = g_kT + (size_t)bb * DD * NKS + j0;
#pragma unroll
            for (int u = 0; u < 4; u++) {
                int idx = u * 256 + t;
                int d = idx >> 4, j = idx & 15;
                o[(size_t)d * NKS + j] = xs[j * 65 + d];
            }
        } else {
            const int rg = row0 + row;
            ((float4*)(g_q + (size_t)rg * DD))[sl] = acc;
        }
    }

    // ===================== Grid barrier (all 512 CTAs resident) ============
    __syncthreads();
    if (t == 0) {
        unsigned s = *(volatile unsigned*)&g_sense;
        __threadfence();
        if (atomicAdd(&g_cnt, 1) == NCTAS - 1) {
            g_cnt = 0;
            __threadfence();
            atomicAdd(&g_sense, 1);
        } else {
            while (*(volatile unsigned*)&g_sense == s) {}
            __threadfence();
        }
    }
    __syncthreads();

    // ===================== Phase B: attention (R4 layout) ==================
    float* S    = sm + S_OFF;      // [4][1032] logits (aliased later as RED)
    float* PD   = sm + PD_OFF;     // [4][2056] duplicated P pairs
    float* QD   = sm + QD_OFF;     // [64][8] (-q) duplicated pairs
    float* Mp   = sm + MP_OFF;     // [4][2]
    float* Sp   = sm + SP_OFF;     // [4][2]

    const int b  = bid >> 7;
    const int qt = bid & 127;

    // stage QD[d][2i..2i+1] = -q[i][d]
    {
        const int d = t >> 2, i = t & 3;
        float v = g_q[(size_t)(b * NQS + qt * 4 + i) * DD + d];
        QD[d * 8 + 2 * i + 0] = -v;
        QD[d * 8 + 2 * i + 1] = -v;
    }
    __syncthreads();

    const float* kTg = g_kT + (size_t)b * DD * NKS;

    // -------- logits: 2 independent key-pair chains per thread --------
    {
        const int j0 = w * 64 + 2 * lane;
        const int j1 = 512 + j0;
        const float* kp0 = kTg + j0;
        const float* kp1 = kTg + j1;

        ull a00 = 0, a01 = 0, a02 = 0, a03 = 0;
        ull a10 = 0, a11 = 0, a12 = 0, a13 = 0;
#pragma unroll 4
        for (int d = 0; d < 64; d++) {
            ull kA = *(const ull*)(kp0 + (size_t)d * NKS);
            ull kB = *(const ull*)(kp1 + (size_t)d * NKS);
            ulonglong2 nq01 = *(const ulonglong2*)(QD + d * 8);
            ulonglong2 nq23 = *(const ulonglong2*)(QD + d * 8 + 4);
            ull u;
            ADD2(u, kA, nq01.x); u &= ABSM; ADD2(a00, a00, u);
            ADD2(u, kA, nq01.y); u &= ABSM; ADD2(a01, a01, u);
            ADD2(u, kA, nq23.x); u &= ABSM; ADD2(a02, a02, u);
            ADD2(u, kA, nq23.y); u &= ABSM; ADD2(a03, a03, u);
            ADD2(u, kB, nq01.x); u &= ABSM; ADD2(a10, a10, u);
            ADD2(u, kB, nq01.y); u &= ABSM; ADD2(a11, a11, u);
            ADD2(u, kB, nq23.x); u &= ABSM; ADD2(a12, a12, u);
            ADD2(u, kB, nq23.y); u &= ABSM; ADD2(a13, a13, u);
        }
        const ull accA[4] = {a00, a01, a02, a03};
        const ull accB[4] = {a10, a11, a12, a13};
#pragma unroll
        for (int q = 0; q < 4; q++) {
            ull a = accA[q], bq = accB[q];
            *(float2*)(S + q * S_STRIDE + j0) =
                make_float2(-__uint_as_float((unsigned)a),
                            -__uint_as_float((unsigned)(a >> 32)));
            *(float2*)(S + q * S_STRIDE + j1) =
                make_float2(-__uint_as_float((unsigned)bq),
                            -__uint_as_float((unsigned)(bq >> 32)));
        }
    }
    __syncthreads();

    // -------- softmax: 2 warps per row --------
    {
        const int row  = w >> 1;
        const int half = w & 1;
        const float* Srow = S + row * S_STRIDE + half * 512;
        float* Prow = PD + row * PD_STRIDE + half * 1024;

        float m = -3.0e38f;
#pragma unroll
        for (int it = 0; it < 16; it++) m = fmaxf(m, Srow[it * 32 + lane]);
#pragma unroll
        for (int o = 16; o; o >>= 1) m = fmaxf(m, __shfl_xor_sync(0xffffffffu, m, o));
        if (lane == 0) Mp[row * 2 + half] = m;
        __syncthreads();
        const float M = fmaxf(Mp[row * 2], Mp[row * 2 + 1]);

        float sum = 0.f;
#pragma unroll
        for (int it = 0; it < 16; it++) {
            float p = __expf(Srow[it * 32 + lane] - M);
            *(float2*)(Prow + 2 * (it * 32 + lane)) = make_float2(p, p);
            sum += p;
        }
#pragma unroll
        for (int o = 16; o; o >>= 1) sum += __shfl_xor_sync(0xffffffffu, sum, o);
        if (lane == 0) Sp[row * 2 + half] = sum;
    }
    __syncthreads();

    // -------- O = P @ r via FFMA2, 8-way K split --------
    const int kg = t >> 5;
    const int qg = (t >> 4) & 1;
    const int dg = t & 15;
    const float* rb  = rv + (size_t)b * NKS * DD + (size_t)kg * 128 * DD + dg * 4;
    const float* PD0 = PD + (qg * 2 + 0) * PD_STRIDE + kg * 256;
    const float* PD1 = PD + (qg * 2 + 1) * PD_STRIDE + kg * 256;

    ull aA0 = 0, aA1 = 0, aB0 = 0, aB1 = 0;
#pragma unroll 4
    for (int kk = 0; kk < 128; kk++) {
        ull p0 = *(const ull*)(PD0 + 2 * kk);
        ull p1 = *(const ull*)(PD1 + 2 * kk);
        ulonglong2 r2 = *(const ulonglong2*)(rb + (size_t)kk * DD);
        FMA2(aA0, p0, r2.x, aA0);
        FMA2(aA1, p0, r2.y, aA1);
        FMA2(aB0, p1, r2.x, aB0);
        FMA2(aB1, p1, r2.y, aB1);
    }

    float4* RED = (float4*)sm;
    {
        float4 vA = make_float4(__uint_as_float((unsigned)aA0),
                                __uint_as_float((unsigned)(aA0 >> 32)),
                                __uint_as_float((unsigned)aA1),
                                __uint_as_float((unsigned)(aA1 >> 32)));
        float4 vB = make_float4(__uint_as_float((unsigned)aB0),
                                __uint_as_float((unsigned)(aB0 >> 32)),
                                __uint_as_float((unsigned)aB1),
                                __uint_as_float((unsigned)(aB1 >> 32)));
        RED[kg * 64 + (qg * 2 + 0) * 16 + dg] = vA;
        RED[kg * 64 + (qg * 2 + 1) * 16 + dg] = vB;
    }
    __syncthreads();

    if (t < 64) {
        const int q = t >> 4, dd = t & 15;
        float4 s = RED[q * 16 + dd];
#pragma unroll
        for (int g = 1; g < 8; g++) {
            float4 v = RED[g * 64 + q * 16 + dd];
            s.x += v.x; s.y += v.y; s.z += v.z; s.w += v.w;
        }
        const float li = 1.0f / (Sp[q * 2] + Sp[q * 2 + 1]);
        s.x *= li; s.y *= li; s.z *= li; s.w *= li;
        ((float4*)(out + (size_t)(b * NQS + qt * 4 + q) * DD))[dd] = s;
    }
}

// ---------------------------------------------------------------------------
extern "C" void kernel_launch(void* const* d_in, const int* in_sizes, int n_in,
                              void* d_out, int out_size)
{
    const float* x1  = (const float*)d_in[0];
    const float* x2  = (const float*)d_in[1];
    const float* r   = (const float*)d_in[2];
    const float* Wk1 = (const float*)d_in[3];
    const float* bk1 = (const float*)d_in[4];
    const float* Wk2 = (const float*)d_in[5];
    const float* bk2 = (const float*)d_in[6];
    const float* Wq1 = (const float*)d_in[7];
    const float* bq1 = (const float*)d_in[8];
    const float* Wq2 = (const float*)d_in[9];
    const float* bq2 = (const float*)d_in[10];
    float* out = (float*)d_out;

    cudaFuncSetAttribute(fused_kernel, cudaFuncAttributeMaxDynamicSharedMemorySize,
                         SMEM_FLOATS * 4);

    fused_kernel<<<NCTAS, 256, SMEM_FLOATS * 4>>>(
        x1, x2, r, Wk1, bk1, Wk2, bk2, Wq1, bq1, Wq2, bq2, out);
}

// round 8
// speedup vs baseline: 1.3304x; 1.0478x over previous
#include <cuda_runtime.h>

#define NB 4
#define NQS 512
#define NKS 1024
#define DD 64
#define NCTAS 1024

typedef unsigned long long ull;

#define ADD2(o,a,b)   asm("add.rn.f32x2 %0, %1, %2;" : "=l"(o) : "l"(a), "l"(b))
#define FMA2(o,a,b,c) asm("fma.rn.f32x2 %0, %1, %2, %3;" : "=l"(o) : "l"(a), "l"(b), "l"(c))
#define PACKDUP(o,f)  asm("mov.b64 %0, {%1, %1};" : "=l"(o) : "f"(f))
#define ABSM 0x7FFFFFFF7FFFFFFFULL

// ---- attn-phase smem (floats) ----
// S rows (in-place P) at 0 and 1032; QD at 2064; RED aliases [0,1024) after sync
#define S0_OFF 0
#define S1_OFF 1032
#define QD_OFF 2064                 // 64*4 = 256 floats
#define MP_OFF 4096                 // 2 rows x 4 warp maxima
#define SP_OFF 4104                 // 2 rows x 2 half sums
// ---- mlp-phase smem ----
// Ws 4096 | b1 64 | b2 64 | xs 520 | hs 520 = 5264 floats = 21056 B (the max)
#define SMEM_BYTES 21056

// Scratch: k transposed per batch (kT[b][d][j]); q row-major.
__device__ __align__(16) float g_kT[NB * DD * NKS];
__device__ __align__(16) float g_q [NB * NQS * DD];

// grid barrier (replay-safe: g_cnt self-resets, g_sense monotonic)
__device__ unsigned g_cnt   = 0;
__device__ unsigned g_sense = 0;

__global__ __launch_bounds__(128, 8) void fused_kernel(
    const float* __restrict__ x1, const float* __restrict__ x2,
    const float* __restrict__ rv,
    const float* __restrict__ Wk1, const float* __restrict__ bk1,
    const float* __restrict__ Wk2, const float* __restrict__ bk2,
    const float* __restrict__ Wq1, const float* __restrict__ bq1,
    const float* __restrict__ Wq2, const float* __restrict__ bq2,
    float* __restrict__ out)
{
    extern __shared__ float sm[];
    const int bid  = blockIdx.x;
    const int t    = threadIdx.x;
    const int lane = t & 31;
    const int w    = t >> 5;

    // =============== Phase A: MLPs (768 CTAs x 8 rows) =====================
    if (bid < 768) {
        float* Ws  = sm;             // 4096 (W1, then W2)
        float* b1s = sm + 4096;      // 64
        float* b2s = sm + 4160;      // 64
        float* xs  = sm + 4224;      // 8*65 = 520
        float* hs  = sm + 4744;      // 520

        const bool keypath = bid < 512;
        const float *x, *W1, *b1, *W2, *b2;
        int row0;
        if (keypath) { x = x1; W1 = Wk1; b1 = bk1; W2 = Wk2; b2 = bk2; row0 = bid * 8; }
        else         { x = x2; W1 = Wq1; b1 = bq1; W2 = Wq2; b2 = bq2; row0 = (bid - 512) * 8; }

        // load W1 + biases + x tile
        for (int idx = t; idx < 1024; idx += 128)
            ((float4*)Ws)[idx] = ((const float4*)W1)[idx];
        if (t < 16) {
            ((float4*)b1s)[t] = ((const float4*)b1)[t];
            ((float4*)b2s)[t] = ((const float4*)b2)[t];
        }
        {   // 8 rows x 16 float4 = 128, one per thread
            int rr = t >> 4, c = t & 15;
            float4 v = ((const float4*)(x + (size_t)(row0 + rr) * DD))[c];
            xs[rr * 65 + c * 4 + 0] = v.x;
            xs[rr * 65 + c * 4 + 1] = v.y;
            xs[rr * 65 + c * 4 + 2] = v.z;
            xs[rr * 65 + c * 4 + 3] = v.w;
        }
        __syncthreads();

        const int row = t >> 4, sl = t & 15;   // 8 rows x 16 slices (4 outs)

        // layer 1
        float4 acc = ((const float4*)b1s)[sl];
        {
            const float* in1 = xs + row * 65;
#pragma unroll 8
            for (int din = 0; din < 64; din++) {
                float xv = in1[din];
                float4 wv = ((const float4*)Ws)[din * 16 + sl];
                acc.x = fmaf(xv, wv.x, acc.x);
                acc.y = fmaf(xv, wv.y, acc.y);
                acc.z = fmaf(xv, wv.z, acc.z);
                acc.w = fmaf(xv, wv.w, acc.w);
            }
        }
        {
            float* h = hs + row * 65 + sl * 4;
            h[0] = fmaxf(acc.x, 0.f); h[1] = fmaxf(acc.y, 0.f);
            h[2] = fmaxf(acc.z, 0.f); h[3] = fmaxf(acc.w, 0.f);
        }
        __syncthreads();

        // overwrite Ws with W2
        for (int idx = t; idx < 1024; idx += 128)
            ((float4*)Ws)[idx] = ((const float4*)W2)[idx];
        __syncthreads();

        // layer 2
        acc = ((const float4*)b2s)[sl];
        {
            const float* in2 = hs + row * 65;
#pragma unroll 8
            for (int din = 0; din < 64; din++) {
                float xv = in2[din];
                float4 wv = ((const float4*)Ws)[din * 16 + sl];
                acc.x = fmaf(xv, wv.x, acc.x);
                acc.y = fmaf(xv, wv.y, acc.y);
                acc.z = fmaf(xv, wv.z, acc.z);
                acc.w = fmaf(xv, wv.w, acc.w);
            }
        }

        if (keypath) {
            __syncthreads();
            {   // stage output rows in xs
                float* o = xs + row * 65 + sl * 4;
                o[0] = acc.x; o[1] = acc.y; o[2] = acc.z; o[3] = acc.w;
            }
            __syncthreads();
            // transposed store g_kT[b][d][j0+j] (8 j per d = one 32B sector)
            const int bb = row0 >> 10;
            const int j0 = row0 & 1023;
            float* o = g_kT + (size_t)bb * DD * NKS + j0;
#pragma unroll
            for (int u = 0; u < 4; u++) {
                int idx = u * 128 + t;
                int d = idx >> 3, j = idx & 7;
                o[(size_t)d * NKS + j] = xs[j * 65 + d];
            }
        } else {
            const int rg = row0 + row;
            ((float4*)(g_q + (size_t)rg * DD))[sl] = acc;
        }
    }

    // =============== Grid barrier (all 1024 CTAs resident) =================
    __syncthreads();
    if (t == 0) {
        unsigned s = *(volatile unsigned*)&g_sense;
        __threadfence();
        if (atomicAdd(&g_cnt, 1) == NCTAS - 1) {
            g_cnt = 0;
            __threadfence();
            atomicAdd(&g_sense, 1);
        } else {
            while (*(volatile unsigned*)&g_sense == s) { __nanosleep(32); }
            __threadfence();
        }
    }
    __syncthreads();

    // =============== Phase B: attention (2 queries per CTA) ================
    float* QD = sm + QD_OFF;   // [64][4]: (-q0,-q0,-q1,-q1) per d
    float* Mp = sm + MP_OFF;   // [2][4]
    float* Sp = sm + SP_OFF;   // [2][2]

    const int b  = bid >> 8;
    const int qt = bid & 255;

    // stage QD
    {
        const int d = t >> 1, i = t & 1;
        float v = g_q[(size_t)(b * NQS + qt * 2 + i) * DD + d];
        QD[d * 4 + 2 * i + 0] = -v;
        QD[d * 4 + 2 * i + 1] = -v;
    }
    __syncthreads();

    const float* kTg = g_kT + (size_t)b * DD * NKS;

    // -------- Phase 1: logits, 4 chains x 2 queries, fused row-max --------
    {
        const int jb = w * 64 + 2 * lane;
        const float* kp = kTg + jb;

        ull a00 = 0, a01 = 0, a10 = 0, a11 = 0;   // chain c, query q -> a{c}{q}
        ull a20 = 0, a21 = 0, a30 = 0, a31 = 0;
#pragma unroll 4
        for (int d = 0; d < 64; d++) {
            const float* kd = kp + (size_t)d * NKS;
            ull k0 = *(const ull*)(kd + 0);
            ull k1 = *(const ull*)(kd + 256);
            ull k2 = *(const ull*)(kd + 512);
            ull k3 = *(const ull*)(kd + 768);
            ulonglong2 nq = *(const ulonglong2*)(QD + d * 4);
            ull u;
            ADD2(u, k0, nq.x); u &= ABSM; ADD2(a00, a00, u);
            ADD2(u, k0, nq.y); u &= ABSM; ADD2(a01, a01, u);
            ADD2(u, k1, nq.x); u &= ABSM; ADD2(a10, a10, u);
            ADD2(u, k1, nq.y); u &= ABSM; ADD2(a11, a11, u);
            ADD2(u, k2, nq.x); u &= ABSM; ADD2(a20, a20, u);
            ADD2(u, k2, nq.y); u &= ABSM; ADD2(a21, a21, u);
            ADD2(u, k3, nq.x); u &= ABSM; ADD2(a30, a30, u);
            ADD2(u, k3, nq.y); u &= ABSM; ADD2(a31, a31, u);
        }

        const ull accs[4][2] = {{a00,a01},{a10,a11},{a20,a21},{a30,a31}};
        float m0 = -3.0e38f, m1 = -3.0e38f;
#pragma unroll
        for (int c = 0; c < 4; c++) {
#pragma unroll
            for (int q = 0; q < 2; q++) {
                ull a = accs[c][q];
                float fl = -__uint_as_float((unsigned)a);
                float fh = -__uint_as_float((unsigned)(a >> 32));
                *(float2*)(sm + q * 1032 + jb + c * 256) = make_float2(fl, fh);
                float fm = fmaxf(fl, fh);
                if (q == 0) m0 = fmaxf(m0, fm); else m1 = fmaxf(m1, fm);
            }
        }
#pragma unroll
        for (int o = 16; o; o >>= 1) {
            m0 = fmaxf(m0, __shfl_xor_sync(0xffffffffu, m0, o));
            m1 = fmaxf(m1, __shfl_xor_sync(0xffffffffu, m1, o));
        }
        if (lane == 0) { Mp[0 * 4 + w] = m0; Mp[1 * 4 + w] = m1; }
    }
    __syncthreads();

    // -------- Phase 2: softmax in place, 2 warps per row --------
    {
        const int row  = w >> 1;
        const int half = w & 1;
        const float M = fmaxf(fmaxf(Mp[row * 4 + 0], Mp[row * 4 + 1]),
                              fmaxf(Mp[row * 4 + 2], Mp[row * 4 + 3]));
        float* Srow = sm + row * 1032 + half * 512;

        float sum = 0.f;
#pragma unroll
        for (int it = 0; it < 16; it++) {
            int j = it * 32 + lane;
            float p = __expf(Srow[j] - M);
            Srow[j] = p;
            sum += p;
        }
#pragma unroll
        for (int o = 16; o; o >>= 1) sum += __shfl_xor_sync(0xffffffffu, sum, o);
        if (lane == 0) Sp[row * 2 + half] = sum;
    }
    __syncthreads();

    // -------- Phase 3: O = P @ r via FFMA2, 8-way K split --------
    const int kg = t >> 4;          // 0..7: 128-key groups
    const int dg = t & 15;          // float4 of output dims
    const float* rb = rv + (size_t)b * NKS * DD + (size_t)kg * 128 * DD + dg * 4;
    const float* P0 = sm + S0_OFF + kg * 128;
    const float* P1 = sm + S1_OFF + kg * 128;

    ull aA0 = 0, aA1 = 0, aB0 = 0, aB1 = 0;
#pragma unroll 4
    for (int kk = 0; kk < 128; kk++) {
        float p0 = P0[kk];           // LDS.32 broadcast among 16 threads
        float p1 = P1[kk];
        ull pd0, pd1;
        PACKDUP(pd0, p0);
        PACKDUP(pd1, p1);
        ulonglong2 r2 = *(const ulonglong2*)(rb + (size_t)kk * DD);
        FMA2(aA0, pd0, r2.x, aA0);
        FMA2(aA1, pd0, r2.y, aA1);
        FMA2(aB0, pd1, r2.x, aB0);
        FMA2(aB1, pd1, r2.y, aB1);
    }
    __syncthreads();                // all P reads done before RED overlays S

    float4* RED = (float4*)sm;      // [8 kg][2 q][16 dg] = 1024 floats
    RED[kg * 32 + 0 * 16 + dg] =
        make_float4(__uint_as_float((unsigned)aA0),
                    __uint_as_float((unsigned)(aA0 >> 32)),
                    __uint_as_float((unsigned)aA1),
                    __uint_as_float((unsigned)(aA1 >> 32)));
    RED[kg * 32 + 1 * 16 + dg] =
        make_float4(__uint_as_float((unsigned)aB0),
                    __uint_as_float((unsigned)(aB0 >> 32)),
                    __uint_as_float((unsigned)aB1),
                    __uint_as_float((unsigned)(aB1 >> 32)));
    __syncthreads();

    if (t < 32) {
        const int q = t >> 4, dd = t & 15;
        float4 s = RED[q * 16 + dd];
#pragma unroll
        for (int g = 1; g < 8; g++) {
            float4 v = RED[g * 32 + q * 16 + dd];
            s.x += v.x; s.y += v.y; s.z += v.z; s.w += v.w;
        }
        const float li = 1.0f / (Sp[q * 2] + Sp[q * 2 + 1]);
        s.x *= li; s.y *= li; s.z *= li; s.w *= li;
        ((float4*)(out + (size_t)(b * NQS + qt * 2 + q) * DD))[dd] = s;
    }
}

// ---------------------------------------------------------------------------
extern "C" void kernel_launch(void* const* d_in, const int* in_sizes, int n_in,
                              void* d_out, int out_size)
{
    const float* x1  = (const float*)d_in[0];
    const float* x2  = (const float*)d_in[1];
    const float* r   = (const float*)d_in[2];
    const float* Wk1 = (const float*)d_in[3];
    const float* bk1 = (const float*)d_in[4];
    const float* Wk2 = (const float*)d_in[5];
    const float* bk2 = (const float*)d_in[6];
    const float* Wq1 = (const float*)d_in[7];
    const float* bq1 = (const float*)d_in[8];
    const float* Wq2 = (const float*)d_in[9];
    const float* bq2 = (const float*)d_in[10];
    float* out = (float*)d_out;

    cudaFuncSetAttribute(fused_kernel, cudaFuncAttributeMaxDynamicSharedMemorySize,
                         SMEM_BYTES);

    fused_kernel<<<NCTAS, 128, SMEM_BYTES>>>(
        x1, x2, r, Wk1, bk1, Wk2, bk2, Wq1, bq1, Wq2, bq2, out);
}